// round 11
// baseline (speedup 1.0000x reference)
#include <cuda_runtime.h>
#include <cuda_bf16.h>
#include <math.h>

// ---------------- problem constants ----------------
#define Bb   2
#define Ss   512
#define Hh   1024
#define NHh  16
#define Dd   64
#define Ll   4
#define FFf  4096
#define Vv   12800
#define NCc  14
#define SPAN 256
#define Rr   512           // 2*SPAN
#define Mm   (Bb*Ss)       // 1024 tokens
#define EPSLN 1e-7f

typedef unsigned short u16;
typedef unsigned int   u32;

// ---------------- static device scratch (no allocation allowed) ----------------
__device__ float g_x   [Mm*Hh];
__device__ float g_sc  [(long)Bb*NHh*Ss*Ss];
__device__ float g_c2p [(long)Bb*NHh*Ss*Rr];
__device__ float g_p2c [(long)Bb*NHh*Ss*Rr];
__device__ float g_tmp [Mm*Hh];
__device__ float g_t   [Mm*Hh];
__device__ float g_part[4L*Mm*Hh];
__device__ float g_logits[Mm*NCc];
__device__ int   g_ic2p[Ss*Ss];
__device__ int   g_ip2c[Ss*Ss];

// bf16 hi/lo activation buffers
__device__ u16 g_xhi[Mm*Hh],  g_xlo[Mm*Hh];
__device__ u16 g_relhi[Rr*Hh], g_rello[Rr*Hh];
__device__ u16 g_qhi[Mm*Hh],  g_qlo[Mm*Hh];
__device__ u16 g_khi[Mm*Hh],  g_klo[Mm*Hh];
__device__ u16 g_vhi[Mm*Hh],  g_vlo[Mm*Hh];
__device__ u16 g_pkhi[Rr*Hh], g_pklo[Rr*Hh];
__device__ u16 g_pqhi[Rr*Hh], g_pqlo[Rr*Hh];
__device__ u16 g_phi[(long)Bb*NHh*Ss*Ss], g_plo[(long)Bb*NHh*Ss*Ss];
__device__ u16 g_ctxhi[Mm*Hh], g_ctxlo[Mm*Hh];
__device__ u16 g_ffhi[Mm*FFf], g_fflo[Mm*FFf];

// bf16 hi/lo weight buffers (all layers)
__device__ u16 g_wqhi[Ll*Hh*Hh], g_wqlo[Ll*Hh*Hh];
__device__ u16 g_wkhi[Ll*Hh*Hh], g_wklo[Ll*Hh*Hh];
__device__ u16 g_wvhi[Ll*Hh*Hh], g_wvlo[Ll*Hh*Hh];
__device__ u16 g_wohi[Ll*Hh*Hh], g_wolo[Ll*Hh*Hh];
__device__ u16 g_w1hi[(long)Ll*Hh*FFf], g_w1lo[(long)Ll*Hh*FFf];
__device__ u16 g_w2hi[(long)Ll*FFf*Hh], g_w2lo[(long)Ll*FFf*Hh];
__device__ u16 g_wthi[Hh*Hh], g_wtlo[Hh*Hh];

// ---------------- helpers ----------------
__device__ __forceinline__ float block_sum(float v, float* red) {
    int tid = threadIdx.x;
    red[tid] = v; __syncthreads();
    #pragma unroll
    for (int s = 128; s > 0; s >>= 1) {
        if (tid < s) red[tid] += red[tid + s];
        __syncthreads();
    }
    float r = red[0]; __syncthreads();
    return r;
}

__device__ __forceinline__ float gelu_exact(float x) {
    return 0.5f * x * (1.0f + erff(x * 0.70710678118654752f));
}

__device__ __forceinline__ void bfsplit(float x, u16& h, u16& l) {
    __nv_bfloat16 bh = __float2bfloat16_rn(x);
    float rem = x - __bfloat162float(bh);
    __nv_bfloat16 bl = __float2bfloat16_rn(rem);
    h = *(u16*)&bh;
    l = *(u16*)&bl;
}

__device__ __forceinline__ void mma16816(float* c,
                                         u32 a0, u32 a1, u32 a2, u32 a3,
                                         u32 b0, u32 b1) {
    asm volatile(
        "mma.sync.aligned.m16n8k16.row.col.f32.bf16.bf16.f32 "
        "{%0,%1,%2,%3},{%4,%5,%6,%7},{%8,%9},{%0,%1,%2,%3};\n"
        : "+f"(c[0]), "+f"(c[1]), "+f"(c[2]), "+f"(c[3])
        : "r"(a0), "r"(a1), "r"(a2), "r"(a3), "r"(b0), "r"(b1));
}

// ---------------- weight splitter (fp32 -> bf16 hi/lo), float4 vectorized ----
__global__ void wsplit_kernel(const float4* __restrict__ src,
                              u16* __restrict__ hi, u16* __restrict__ lo, int n4) {
    int i = blockIdx.x * blockDim.x + threadIdx.x;
    if (i >= n4) return;
    float4 v = src[i];
    u16 h0,h1,h2,h3,l0,l1,l2,l3;
    bfsplit(v.x,h0,l0); bfsplit(v.y,h1,l1); bfsplit(v.z,h2,l2); bfsplit(v.w,h3,l3);
    *(uint2*)(hi + 4L*i) = make_uint2((u32)h0 | ((u32)h1<<16), (u32)h2 | ((u32)h3<<16));
    *(uint2*)(lo + 4L*i) = make_uint2((u32)l0 | ((u32)l1<<16), (u32)l2 | ((u32)l3<<16));
}

// ================= smem layouts =================
struct SmemNNb {
    u16 Ahi[128][40]; u16 Alo[128][40];
    u16 Bhi[32][136]; u16 Blo[32][136];
};
struct SmemNTb {
    u16 Ahi[128][40]; u16 Alo[128][40];
    u16 Bhi[128][40]; u16 Blo[128][40];
};
struct SmemCtxb {
    u16 Ahi[128][40]; u16 Alo[128][40];
    u16 Bhi[64][40];  u16 Blo[64][40];
};

// ---- loader: 128 rows x 32 k of bf16 hi/lo into [rows][40]-padded smem ----
__device__ __forceinline__ void load_rows_bf16(
    u16 (*dhi)[40], u16 (*dlo)[40],
    const u16* __restrict__ ghi, const u16* __restrict__ glo,
    long base, int lda, int k0) {
    int t = threadIdx.x;
    int m = t >> 1, half = t & 1;
    long off = base + (long)m * lda + k0 + half * 16;
    uint4 h0 = *(const uint4*)(ghi + off);
    uint4 h1 = *(const uint4*)(ghi + off + 8);
    uint4 l0 = *(const uint4*)(glo + off);
    uint4 l1 = *(const uint4*)(glo + off + 8);
    int c = half * 16;
    *(uint2*)&dhi[m][c+0]  = make_uint2(h0.x, h0.y);
    *(uint2*)&dhi[m][c+4]  = make_uint2(h0.z, h0.w);
    *(uint2*)&dhi[m][c+8]  = make_uint2(h1.x, h1.y);
    *(uint2*)&dhi[m][c+12] = make_uint2(h1.z, h1.w);
    *(uint2*)&dlo[m][c+0]  = make_uint2(l0.x, l0.y);
    *(uint2*)&dlo[m][c+4]  = make_uint2(l0.z, l0.w);
    *(uint2*)&dlo[m][c+8]  = make_uint2(l1.x, l1.y);
    *(uint2*)&dlo[m][c+12] = make_uint2(l1.z, l1.w);
}

// ---- loader: 32 k x 128 n (k-major) into [32][136]-padded smem ----
__device__ __forceinline__ void load_b_nn_bf16(
    u16 (*dhi)[136], u16 (*dlo)[136],
    const u16* __restrict__ ghi, const u16* __restrict__ glo,
    long base, int N) {
    int t = threadIdx.x;
    int kk = t >> 3, n16 = (t & 7) * 16;
    long off = base + (long)kk * N + n16;
    uint4 h0 = *(const uint4*)(ghi + off);
    uint4 h1 = *(const uint4*)(ghi + off + 8);
    uint4 l0 = *(const uint4*)(glo + off);
    uint4 l1 = *(const uint4*)(glo + off + 8);
    *(uint4*)&dhi[kk][n16]   = h0;
    *(uint4*)&dhi[kk][n16+8] = h1;
    *(uint4*)&dlo[kk][n16]   = l0;
    *(uint4*)&dlo[kk][n16+8] = l1;
}

// ---- compute: NN (B gathered from k-major smem) ----
__device__ __forceinline__ void mma_compute_nn(SmemNNb& sm, float acc[64],
                                               int wm, int wn, int gg, int qq) {
    #pragma unroll
    for (int ks = 0; ks < 32; ks += 16) {
        u32 ah[2][4], al[2][4];
        #pragma unroll
        for (int mt = 0; mt < 2; mt++) {
            int r  = wm * 32 + mt * 16 + gg;
            int kc = ks + 2 * qq;
            ah[mt][0] = *(u32*)&sm.Ahi[r    ][kc    ];
            ah[mt][1] = *(u32*)&sm.Ahi[r + 8][kc    ];
            ah[mt][2] = *(u32*)&sm.Ahi[r    ][kc + 8];
            ah[mt][3] = *(u32*)&sm.Ahi[r + 8][kc + 8];
            al[mt][0] = *(u32*)&sm.Alo[r    ][kc    ];
            al[mt][1] = *(u32*)&sm.Alo[r + 8][kc    ];
            al[mt][2] = *(u32*)&sm.Alo[r    ][kc + 8];
            al[mt][3] = *(u32*)&sm.Alo[r + 8][kc + 8];
        }
        #pragma unroll
        for (int nt = 0; nt < 8; nt++) {
            int n  = wn * 64 + nt * 8 + gg;
            int kb = ks + 2 * qq;
            u32 bh0 = (u32)sm.Bhi[kb    ][n] | ((u32)sm.Bhi[kb + 1][n] << 16);
            u32 bh1 = (u32)sm.Bhi[kb + 8][n] | ((u32)sm.Bhi[kb + 9][n] << 16);
            u32 bl0 = (u32)sm.Blo[kb    ][n] | ((u32)sm.Blo[kb + 1][n] << 16);
            u32 bl1 = (u32)sm.Blo[kb + 8][n] | ((u32)sm.Blo[kb + 9][n] << 16);
            #pragma unroll
            for (int mt = 0; mt < 2; mt++) {
                float* c = acc + (mt * 8 + nt) * 4;
                mma16816(c, ah[mt][0], ah[mt][1], ah[mt][2], ah[mt][3], bh0, bh1);
                mma16816(c, ah[mt][0], ah[mt][1], ah[mt][2], ah[mt][3], bl0, bl1);
                mma16816(c, al[mt][0], al[mt][1], al[mt][2], al[mt][3], bh0, bh1);
            }
        }
    }
}

// ---- compute: NT (B aligned from [n][40] smem) ----
__device__ __forceinline__ void mma_compute_nt(SmemNTb& sm, float acc[64],
                                               int wm, int wn, int gg, int qq) {
    #pragma unroll
    for (int ks = 0; ks < 32; ks += 16) {
        u32 ah[2][4], al[2][4];
        #pragma unroll
        for (int mt = 0; mt < 2; mt++) {
            int r  = wm * 32 + mt * 16 + gg;
            int kc = ks + 2 * qq;
            ah[mt][0] = *(u32*)&sm.Ahi[r    ][kc    ];
            ah[mt][1] = *(u32*)&sm.Ahi[r + 8][kc    ];
            ah[mt][2] = *(u32*)&sm.Ahi[r    ][kc + 8];
            ah[mt][3] = *(u32*)&sm.Ahi[r + 8][kc + 8];
            al[mt][0] = *(u32*)&sm.Alo[r    ][kc    ];
            al[mt][1] = *(u32*)&sm.Alo[r + 8][kc    ];
            al[mt][2] = *(u32*)&sm.Alo[r    ][kc + 8];
            al[mt][3] = *(u32*)&sm.Alo[r + 8][kc + 8];
        }
        #pragma unroll
        for (int nt = 0; nt < 8; nt++) {
            int n  = wn * 64 + nt * 8 + gg;
            int kb = ks + 2 * qq;
            u32 bh0 = *(u32*)&sm.Bhi[n][kb];
            u32 bh1 = *(u32*)&sm.Bhi[n][kb + 8];
            u32 bl0 = *(u32*)&sm.Blo[n][kb];
            u32 bl1 = *(u32*)&sm.Blo[n][kb + 8];
            #pragma unroll
            for (int mt = 0; mt < 2; mt++) {
                float* c = acc + (mt * 8 + nt) * 4;
                mma16816(c, ah[mt][0], ah[mt][1], ah[mt][2], ah[mt][3], bh0, bh1);
                mma16816(c, ah[mt][0], ah[mt][1], ah[mt][2], ah[mt][3], bl0, bl1);
                mma16816(c, al[mt][0], al[mt][1], al[mt][2], al[mt][3], bh0, bh1);
            }
        }
    }
}

// ---- epilogues ----
__device__ void mma_epi_raw(float* __restrict__ C, float acc[64],
                            int row0, int col0, int ldc) {
    int tid = threadIdx.x, lane = tid & 31, warp = tid >> 5;
    int wm = warp & 3, wn = warp >> 2;
    int gg = lane >> 2, qq = lane & 3;
    #pragma unroll
    for (int mt = 0; mt < 2; mt++)
        #pragma unroll
        for (int nt = 0; nt < 8; nt++) {
            int row = row0 + wm * 32 + mt * 16 + gg;
            int col = col0 + wn * 64 + nt * 8 + 2 * qq;
            const float* c = acc + (mt * 8 + nt) * 4;
            *(float2*)(C + (long)row * ldc + col)       = make_float2(c[0], c[1]);
            *(float2*)(C + (long)(row + 8) * ldc + col) = make_float2(c[2], c[3]);
        }
}

// bias(+act) then bf16 hi/lo split store
__device__ void mma_epi_bias_split(u16* __restrict__ Chi, u16* __restrict__ Clo,
                                   const float* __restrict__ bias, float acc[64],
                                   int row0, int col0, int ldc, int act) {
    int tid = threadIdx.x, lane = tid & 31, warp = tid >> 5;
    int wm = warp & 3, wn = warp >> 2;
    int gg = lane >> 2, qq = lane & 3;
    #pragma unroll
    for (int mt = 0; mt < 2; mt++)
        #pragma unroll
        for (int nt = 0; nt < 8; nt++) {
            int row = row0 + wm * 32 + mt * 16 + gg;
            int col = col0 + wn * 64 + nt * 8 + 2 * qq;
            const float* c = acc + (mt * 8 + nt) * 4;
            float v0 = c[0] + bias[col],   v1 = c[1] + bias[col+1];
            float v2 = c[2] + bias[col],   v3 = c[3] + bias[col+1];
            if (act) { v0 = gelu_exact(v0); v1 = gelu_exact(v1);
                       v2 = gelu_exact(v2); v3 = gelu_exact(v3); }
            u16 h0,h1,h2,h3,l0,l1,l2,l3;
            bfsplit(v0,h0,l0); bfsplit(v1,h1,l1); bfsplit(v2,h2,l2); bfsplit(v3,h3,l3);
            *(u32*)(Chi + (long)row * ldc + col)       = (u32)h0 | ((u32)h1 << 16);
            *(u32*)(Clo + (long)row * ldc + col)       = (u32)l0 | ((u32)l1 << 16);
            *(u32*)(Chi + (long)(row + 8) * ldc + col) = (u32)h2 | ((u32)h3 << 16);
            *(u32*)(Clo + (long)(row + 8) * ldc + col) = (u32)l2 | ((u32)l3 << 16);
        }
}

// ================= kernels =================

// fused q/k/v + pos_k/pos_q projections (z=0..4)
__global__ __launch_bounds__(256, 2) void qkvpos_mma_b(
    const u16* __restrict__ xhi, const u16* __restrict__ xlo,
    const u16* __restrict__ relhi, const u16* __restrict__ rello,
    const u16* __restrict__ wqhi, const u16* __restrict__ wqlo,
    const u16* __restrict__ wkhi, const u16* __restrict__ wklo,
    const u16* __restrict__ wvhi, const u16* __restrict__ wvlo,
    const float* __restrict__ bq, const float* __restrict__ bk, const float* __restrict__ bv,
    u16* qhi, u16* qlo, u16* khi, u16* klo, u16* vhi, u16* vlo,
    u16* pkhi, u16* pklo, u16* pqhi, u16* pqlo) {
    __shared__ SmemNNb sm;
    int z = blockIdx.z;
    const u16 *Ahi, *Alo, *Whi, *Wlo; const float* bias; u16 *Chi, *Clo;
    if (z == 0)      { Ahi=xhi; Alo=xlo; Whi=wqhi; Wlo=wqlo; bias=bq; Chi=qhi; Clo=qlo; }
    else if (z == 1) { Ahi=xhi; Alo=xlo; Whi=wkhi; Wlo=wklo; bias=bk; Chi=khi; Clo=klo; }
    else if (z == 2) { Ahi=xhi; Alo=xlo; Whi=wvhi; Wlo=wvlo; bias=bv; Chi=vhi; Clo=vlo; }
    else if (z == 3) { if (blockIdx.y >= 4) return; Ahi=relhi; Alo=rello; Whi=wkhi; Wlo=wklo; bias=bk; Chi=pkhi; Clo=pklo; }
    else             { if (blockIdx.y >= 4) return; Ahi=relhi; Alo=rello; Whi=wqhi; Wlo=wqlo; bias=bq; Chi=pqhi; Clo=pqlo; }
    int tid = threadIdx.x, lane = tid & 31, warp = tid >> 5;
    int wm = warp & 3, wn = warp >> 2, gg = lane >> 2, qq = lane & 3;
    int row0 = blockIdx.y * 128, col0 = blockIdx.x * 128;
    float acc[64] = {};
    for (int k0 = 0; k0 < Hh; k0 += 32) {
        load_rows_bf16(sm.Ahi, sm.Alo, Ahi, Alo, (long)row0 * Hh, Hh, k0);
        load_b_nn_bf16(sm.Bhi, sm.Blo, Whi, Wlo, (long)k0 * Hh + col0, Hh);
        __syncthreads();
        mma_compute_nn(sm, acc, wm, wn, gg, qq);
        __syncthreads();
    }
    mma_epi_bias_split(Chi, Clo, bias, acc, row0, col0, Hh, 0);
}

// generic NN GEMM, bias(+gelu), split-store output (FFN1)
__global__ __launch_bounds__(256, 2) void gemm_mma_b(
    const u16* __restrict__ Ahi, const u16* __restrict__ Alo,
    const u16* __restrict__ Whi, const u16* __restrict__ Wlo,
    const float* __restrict__ bias, u16* Chi, u16* Clo, int N, int K, int act) {
    __shared__ SmemNNb sm;
    int tid = threadIdx.x, lane = tid & 31, warp = tid >> 5;
    int wm = warp & 3, wn = warp >> 2, gg = lane >> 2, qq = lane & 3;
    int row0 = blockIdx.y * 128, col0 = blockIdx.x * 128;
    float acc[64] = {};
    for (int k0 = 0; k0 < K; k0 += 32) {
        load_rows_bf16(sm.Ahi, sm.Alo, Ahi, Alo, (long)row0 * K, K, k0);
        load_b_nn_bf16(sm.Bhi, sm.Blo, Whi, Wlo, (long)k0 * N + col0, N);
        __syncthreads();
        mma_compute_nn(sm, acc, wm, wn, gg, qq);
        __syncthreads();
    }
    mma_epi_bias_split(Chi, Clo, bias, acc, row0, col0, N, act);
}

// split-K NN GEMM -> fp32 partials (deterministic; z = k-chunk)
__global__ __launch_bounds__(256, 2) void gemm_mma_split_b(
    const u16* __restrict__ Ahi, const u16* __restrict__ Alo,
    const u16* __restrict__ Whi, const u16* __restrict__ Wlo,
    float* P, int N, int K, int nsplit) {
    __shared__ SmemNNb sm;
    int z = blockIdx.z;
    int kc = K / nsplit;
    int tid = threadIdx.x, lane = tid & 31, warp = tid >> 5;
    int wm = warp & 3, wn = warp >> 2, gg = lane >> 2, qq = lane & 3;
    int row0 = blockIdx.y * 128, col0 = blockIdx.x * 128;
    float acc[64] = {};
    for (int k0 = z * kc; k0 < (z + 1) * kc; k0 += 32) {
        load_rows_bf16(sm.Ahi, sm.Alo, Ahi, Alo, (long)row0 * K, K, k0);
        load_b_nn_bf16(sm.Bhi, sm.Blo, Whi, Wlo, (long)k0 * N + col0, N);
        __syncthreads();
        mma_compute_nn(sm, acc, wm, wn, gg, qq);
        __syncthreads();
    }
    int M = gridDim.y * 128;
    mma_epi_raw(P + (long)z * M * N, acc, row0, col0, N);
}

__global__ void reduce_bias_kernel(const float* __restrict__ P, const float* __restrict__ bias,
                                   float* __restrict__ C, int M, int N, int nsplit, int act) {
    int i = blockIdx.x * blockDim.x + threadIdx.x;
    long sz = (long)M * N;
    if (i >= sz) return;
    float s = 0.f;
    for (int p = 0; p < nsplit; p++) s += P[(long)p * sz + i];
    s += bias[i & (N - 1)];
    if (act) s = gelu_exact(s);
    C[i] = s;
}

// fused scores / c2p / p2c NT batched (z = type*32 + bh), bf16 inputs
__global__ __launch_bounds__(256, 2) void att_mma_b(
    const u16* __restrict__ qhi, const u16* __restrict__ qlo,
    const u16* __restrict__ khi, const u16* __restrict__ klo,
    const u16* __restrict__ pkhi, const u16* __restrict__ pklo,
    const u16* __restrict__ pqhi, const u16* __restrict__ pqlo,
    float* sc, float* c2p, float* p2c) {
    __shared__ SmemNTb sm;
    int z = blockIdx.z;
    int type = z >> 5;
    int bh = z & 31;
    int b = bh >> 4, h = bh & 15;
    long Aoff = (long)b * Ss * Hh + (long)h * Dd;
    const u16 *Ahi, *Alo, *Bhi_g, *Blo_g;
    long Boff;
    if (type == 0)      { Ahi = qhi; Alo = qlo; Bhi_g = khi;  Blo_g = klo;  Boff = Aoff; }
    else if (type == 1) { Ahi = qhi; Alo = qlo; Bhi_g = pkhi; Blo_g = pklo; Boff = (long)h * Dd; }
    else                { Ahi = khi; Alo = klo; Bhi_g = pqhi; Blo_g = pqlo; Boff = (long)h * Dd; }
    float* C = (type == 0 ? sc : (type == 1 ? c2p : p2c)) + (long)bh * Ss * 512;
    int tid = threadIdx.x, lane = tid & 31, warp = tid >> 5;
    int wm = warp & 3, wn = warp >> 2, gg = lane >> 2, qq = lane & 3;
    int row0 = blockIdx.y * 128, col0 = blockIdx.x * 128;
    float acc[64] = {};
    #pragma unroll
    for (int k0 = 0; k0 < Dd; k0 += 32) {
        load_rows_bf16(sm.Ahi, sm.Alo, Ahi, Alo, Aoff + (long)row0 * Hh, Hh, k0);
        load_rows_bf16(sm.Bhi, sm.Blo, Bhi_g, Blo_g, Boff + (long)col0 * Hh, Hh, k0);
        __syncthreads();
        mma_compute_nt(sm, acc, wm, wn, gg, qq);
        __syncthreads();
    }
    mma_epi_raw(C, acc, row0, col0, 512);
}

// ctx = probs @ v, bf16 inputs, split-store output
__global__ __launch_bounds__(256, 2) void ctx_mma_b(
    const u16* __restrict__ phi, const u16* __restrict__ plo,
    const u16* __restrict__ vhi, const u16* __restrict__ vlo,
    u16* __restrict__ ctxhi, u16* __restrict__ ctxlo) {
    __shared__ SmemCtxb sm;
    int bh = blockIdx.z;
    int b = bh >> 4, h = bh & 15;
    long Aoff = (long)bh * Ss * Ss;
    long Voff = (long)b * Ss * Hh + (long)h * Dd;
    int tid = threadIdx.x, lane = tid & 31, warp = tid >> 5;
    int wm = warp & 3, wn = warp >> 2, gg = lane >> 2, qq = lane & 3;
    int row0 = blockIdx.y * 128;
    float acc[32] = {};
    for (int k0 = 0; k0 < Ss; k0 += 32) {
        load_rows_bf16(sm.Ahi, sm.Alo, phi, plo, Aoff + (long)row0 * Ss, Ss, k0);
        {   // v tile: 32 s-rows x 64 d -> transposed smem [d][s] with rotation
            int kk = tid >> 3, n8 = (tid & 7) * 8;
            long off = Voff + (long)(k0 + kk) * Hh + n8;
            uint4 bh4 = *(const uint4*)(vhi + off);
            uint4 bl4 = *(const uint4*)(vlo + off);
            const u16* ph = (const u16*)&bh4;
            const u16* pl = (const u16*)&bl4;
            int rot = tid & 7;
            #pragma unroll
            for (int j = 0; j < 8; j++) {
                int jj = (j + rot) & 7;
                sm.Bhi[n8 + jj][kk] = ph[jj];
                sm.Blo[n8 + jj][kk] = pl[jj];
            }
        }
        __syncthreads();
        #pragma unroll
        for (int ks = 0; ks < 32; ks += 16) {
            u32 ah[2][4], al[2][4];
            #pragma unroll
            for (int mt = 0; mt < 2; mt++) {
                int r  = wm * 32 + mt * 16 + gg;
                int kc = ks + 2 * qq;
                ah[mt][0] = *(u32*)&sm.Ahi[r    ][kc    ];
                ah[mt][1] = *(u32*)&sm.Ahi[r + 8][kc    ];
                ah[mt][2] = *(u32*)&sm.Ahi[r    ][kc + 8];
                ah[mt][3] = *(u32*)&sm.Ahi[r + 8][kc + 8];
                al[mt][0] = *(u32*)&sm.Alo[r    ][kc    ];
                al[mt][1] = *(u32*)&sm.Alo[r + 8][kc    ];
                al[mt][2] = *(u32*)&sm.Alo[r    ][kc + 8];
                al[mt][3] = *(u32*)&sm.Alo[r + 8][kc + 8];
            }
            #pragma unroll
            for (int nt = 0; nt < 4; nt++) {
                int n  = wn * 32 + nt * 8 + gg;
                int kb = ks + 2 * qq;
                u32 bh0 = *(u32*)&sm.Bhi[n][kb];
                u32 bh1 = *(u32*)&sm.Bhi[n][kb + 8];
                u32 bl0 = *(u32*)&sm.Blo[n][kb];
                u32 bl1 = *(u32*)&sm.Blo[n][kb + 8];
                #pragma unroll
                for (int mt = 0; mt < 2; mt++) {
                    float* c = acc + (mt * 4 + nt) * 4;
                    mma16816(c, ah[mt][0], ah[mt][1], ah[mt][2], ah[mt][3], bh0, bh1);
                    mma16816(c, ah[mt][0], ah[mt][1], ah[mt][2], ah[mt][3], bl0, bl1);
                    mma16816(c, al[mt][0], al[mt][1], al[mt][2], al[mt][3], bh0, bh1);
                }
            }
        }
        __syncthreads();
    }
    #pragma unroll
    for (int mt = 0; mt < 2; mt++)
        #pragma unroll
        for (int nt = 0; nt < 4; nt++) {
            int row = row0 + wm * 32 + mt * 16 + gg;
            int col = wn * 32 + nt * 8 + 2 * qq;
            const float* c = acc + (mt * 4 + nt) * 4;
            long o0 = Voff - (long)h * Dd + (long)row * 0;  // (unused guard)
            (void)o0;
            long base = (long)b * Ss * Hh + (long)h * Dd;
            u16 h0,h1,h2,h3,l0,l1,l2,l3;
            bfsplit(c[0],h0,l0); bfsplit(c[1],h1,l1); bfsplit(c[2],h2,l2); bfsplit(c[3],h3,l3);
            *(u32*)(ctxhi + base + (long)row * Hh + col)       = (u32)h0 | ((u32)h1 << 16);
            *(u32*)(ctxlo + base + (long)row * Hh + col)       = (u32)l0 | ((u32)l1 << 16);
            *(u32*)(ctxhi + base + (long)(row + 8) * Hh + col) = (u32)h2 | ((u32)h3 << 16);
            *(u32*)(ctxlo + base + (long)(row + 8) * Hh + col) = (u32)l2 | ((u32)l3 << 16);
        }
}

// ---------------- relative-position bucket indices ----------------
__global__ void idx_kernel(int* c2pidx, int* p2cidx) {
    int t = blockIdx.x * blockDim.x + threadIdx.x;
    if (t >= Ss * Ss) return;
    int q = t / Ss, k = t % Ss;
    int rel = q - k;
    const int mid = 128;
    int ap = (rel < mid && rel > -mid) ? (mid - 1) : (rel < 0 ? -rel : rel);
    int bucket;
    if (ap <= mid) {
        bucket = rel;
    } else {
        const float divisor = (float)1.3843393288235763;  // np.log(511/128) as f32
        float lp = ceilf(logf((float)ap / 128.0f) / divisor * 127.0f) + 128.0f;
        float sgn = (rel > 0) ? 1.0f : ((rel < 0) ? -1.0f : 0.0f);
        bucket = (int)(lp * sgn);
    }
    int c = bucket + SPAN;  c = c < 0 ? 0 : (c > 2 * SPAN - 1 ? 2 * SPAN - 1 : c);
    int p = -bucket + SPAN; p = p < 0 ? 0 : (p > 2 * SPAN - 1 ? 2 * SPAN - 1 : p);
    c2pidx[t] = c;
    p2cidx[t] = p;
}

// ---------------- embedding: x = LN(word_emb[ids]) * mask (+ hi/lo) ----------
__global__ void embed_kernel(const float* __restrict__ wemb, const int* __restrict__ ids,
                             const int* __restrict__ amask,
                             const float* __restrict__ s, const float* __restrict__ bb,
                             float* __restrict__ out, u16* __restrict__ ohi, u16* __restrict__ olo) {
    __shared__ float red[256];
    int m = blockIdx.x, tid = threadIdx.x;
    const float* in = wemb + (long)ids[m] * Hh;
    float v[4];
    #pragma unroll
    for (int i = 0; i < 4; i++) v[i] = in[tid + i * 256];
    float sum = 0.f;
    #pragma unroll
    for (int i = 0; i < 4; i++) sum += v[i];
    float mu = block_sum(sum, red) * (1.0f / Hh);
    float var = 0.f;
    #pragma unroll
    for (int i = 0; i < 4; i++) { float d = v[i] - mu; var += d * d; }
    float vt = block_sum(var, red) * (1.0f / Hh);
    float inv = rsqrtf(vt + EPSLN);
    float mk = amask[m] ? 1.0f : 0.0f;
    #pragma unroll
    for (int i = 0; i < 4; i++) {
        int c = tid + i * 256;
        float o = ((v[i] - mu) * inv * s[c] + bb[c]) * mk;
        out[(long)m * Hh + c] = o;
        u16 h, l; bfsplit(o, h, l);
        ohi[(long)m * Hh + c] = h;
        olo[(long)m * Hh + c] = l;
    }
}

// ---------------- LayerNorm writing bf16 hi/lo only (rel embeddings) ---------
__global__ void ln_split_kernel(const float* __restrict__ in,
                                const float* __restrict__ s, const float* __restrict__ bb,
                                u16* __restrict__ ohi, u16* __restrict__ olo) {
    __shared__ float red[256];
    int m = blockIdx.x, tid = threadIdx.x;
    const float* ir = in + (long)m * Hh;
    float v[4];
    #pragma unroll
    for (int i = 0; i < 4; i++) v[i] = ir[tid + i * 256];
    float sum = 0.f;
    #pragma unroll
    for (int i = 0; i < 4; i++) sum += v[i];
    float mu = block_sum(sum, red) * (1.0f / Hh);
    float var = 0.f;
    #pragma unroll
    for (int i = 0; i < 4; i++) { float d = v[i] - mu; var += d * d; }
    float vt = block_sum(var, red) * (1.0f / Hh);
    float inv = rsqrtf(vt + EPSLN);
    #pragma unroll
    for (int i = 0; i < 4; i++) {
        int c = tid + i * 256;
        float o = (v[i] - mu) * inv * s[c] + bb[c];
        u16 h, l; bfsplit(o, h, l);
        ohi[(long)m * Hh + c] = h;
        olo[(long)m * Hh + c] = l;
    }
}

// ---------------- plain fp32 row LayerNorm (head t) ----------------
__global__ void ln_kernel(const float* __restrict__ in, float* __restrict__ out,
                          const float* __restrict__ s, const float* __restrict__ bb) {
    __shared__ float red[256];
    int m = blockIdx.x, tid = threadIdx.x;
    const float* ir = in + (long)m * Hh;
    float v[4];
    #pragma unroll
    for (int i = 0; i < 4; i++) v[i] = ir[tid + i * 256];
    float sum = 0.f;
    #pragma unroll
    for (int i = 0; i < 4; i++) sum += v[i];
    float mu = block_sum(sum, red) * (1.0f / Hh);
    float var = 0.f;
    #pragma unroll
    for (int i = 0; i < 4; i++) { float d = v[i] - mu; var += d * d; }
    float vt = block_sum(var, red) * (1.0f / Hh);
    float inv = rsqrtf(vt + EPSLN);
    #pragma unroll
    for (int i = 0; i < 4; i++) {
        int c = tid + i * 256;
        out[(long)m * Hh + c] = (v[i] - mu) * inv * s[c] + bb[c];
    }
}

// ---------------- residual + LayerNorm: h = LN(h + y), + hi/lo split ---------
__global__ void add_ln_split_kernel(float* __restrict__ h, const float* __restrict__ y,
                                    const float* __restrict__ s, const float* __restrict__ bb,
                                    u16* __restrict__ ohi, u16* __restrict__ olo) {
    __shared__ float red[256];
    int m = blockIdx.x, tid = threadIdx.x;
    long base = (long)m * Hh;
    float v[4];
    #pragma unroll
    for (int i = 0; i < 4; i++) { int c = tid + i * 256; v[i] = h[base + c] + y[base + c]; }
    float sum = 0.f;
    #pragma unroll
    for (int i = 0; i < 4; i++) sum += v[i];
    float mu = block_sum(sum, red) * (1.0f / Hh);
    float var = 0.f;
    #pragma unroll
    for (int i = 0; i < 4; i++) { float d = v[i] - mu; var += d * d; }
    float vt = block_sum(var, red) * (1.0f / Hh);
    float inv = rsqrtf(vt + EPSLN);
    #pragma unroll
    for (int i = 0; i < 4; i++) {
        int c = tid + i * 256;
        float o = (v[i] - mu) * inv * s[c] + bb[c];
        h[base + c] = o;
        u16 hh, ll; bfsplit(o, hh, ll);
        ohi[base + c] = hh;
        olo[base + c] = ll;
    }
}

// ---------------- small-N SGEMM (decoder head, N=14) ----------------
#define BM 64
#define BN 64
#define BK 16
__global__ void gemm_bias_kernel(const float* __restrict__ A, const float* __restrict__ W,
                                 const float* __restrict__ bias, float* __restrict__ C,
                                 int M, int N, int K, int act) {
    __shared__ float As[BK][BM];
    __shared__ float Bs[BK][BN];
    int tid = threadIdx.x;
    int tx = tid & 15, ty = tid >> 4;
    int row0 = blockIdx.y * BM, col0 = blockIdx.x * BN;
    float acc[4][4] = {};
    for (int k0 = 0; k0 < K; k0 += BK) {
        #pragma unroll
        for (int i = 0; i < 4; i++) {
            int idx = tid + i * 256;
            int kk = idx >> 6, mm = idx & 63;
            As[kk][mm] = A[(long)(row0 + mm) * K + k0 + kk];
        }
        #pragma unroll
        for (int i = 0; i < 4; i++) {
            int idx = tid + i * 256;
            int kk = idx >> 6, nn = idx & 63;
            int col = col0 + nn;
            Bs[kk][nn] = (col < N) ? W[(long)(k0 + kk) * N + col] : 0.0f;
        }
        __syncthreads();
        #pragma unroll
        for (int kk = 0; kk < BK; kk++) {
            float a[4], b[4];
            #pragma unroll
            for (int i = 0; i < 4; i++) a[i] = As[kk][ty * 4 + i];
            #pragma unroll
            for (int j = 0; j < 4; j++) b[j] = Bs[kk][tx * 4 + j];
            #pragma unroll
            for (int i = 0; i < 4; i++)
                #pragma unroll
                for (int j = 0; j < 4; j++)
                    acc[i][j] += a[i] * b[j];
        }
        __syncthreads();
    }
    #pragma unroll
    for (int i = 0; i < 4; i++) {
        int r = row0 + ty * 4 + i;
        #pragma unroll
        for (int j = 0; j < 4; j++) {
            int c = col0 + tx * 4 + j;
            if (c < N) {
                float v = acc[i][j] + bias[c];
                if (act == 1) v = gelu_exact(v);
                C[(long)r * N + c] = v;
            }
        }
    }
}

// ---------------- fused gather + scale + mask + softmax -> probs hi/lo -------
__global__ void softmax_kernel(const float* __restrict__ scores,
                               const float* __restrict__ c2p, const float* __restrict__ p2c,
                               const int* __restrict__ ic2p, const int* __restrict__ ip2c,
                               const int* __restrict__ amask,
                               u16* __restrict__ phi, u16* __restrict__ plo) {
    __shared__ float sm[Ss];
    __shared__ float red[256];
    int q  = blockIdx.x;
    int bh = blockIdx.y;
    int b  = bh / NHh;
    int tid = threadIdx.x;
    const float inv_scale = 0.07216878364870322f;  // 1/sqrt(3*D)
    int maskq = amask[b * Ss + q];
    const float* row = scores + ((long)bh * Ss + q) * Ss;
    const float* c2pr = c2p + ((long)bh * Ss + q) * Rr;
    const float* p2cb = p2c + (long)bh * Ss * Rr;
    u16* hrow = phi + ((long)bh * Ss + q) * Ss;
    u16* lrow = plo + ((long)bh * Ss + q) * Ss;

    for (int k = tid; k < Ss; k += 256) {
        float s;
        if (maskq && amask[b * Ss + k]) {
            s = (row[k] + c2pr[ic2p[q * Ss + k]] + p2cb[(long)k * Rr + ip2c[k * Ss + q]]) * inv_scale;
        } else {
            s = -INFINITY;
        }
        sm[k] = s;
    }
    __syncthreads();
    float mx = -INFINITY;
    for (int k = tid; k < Ss; k += 256) mx = fmaxf(mx, sm[k]);
    red[tid] = mx; __syncthreads();
    #pragma unroll
    for (int s = 128; s > 0; s >>= 1) {
        if (tid < s) red[tid] = fmaxf(red[tid], red[tid + s]);
        __syncthreads();
    }
    mx = red[0]; __syncthreads();
    if (mx == -INFINITY) {
        for (int k = tid; k < Ss; k += 256) { hrow[k] = 0; lrow[k] = 0; }
        return;
    }
    float sum = 0.f;
    for (int k = tid; k < Ss; k += 256) {
        float e = expf(sm[k] - mx);
        sm[k] = e;
        sum += e;
    }
    float tot = block_sum(sum, red);
    float inv = 1.0f / tot;
    for (int k = tid; k < Ss; k += 256) {
        u16 h, l; bfsplit(sm[k] * inv, h, l);
        hrow[k] = h; lrow[k] = l;
    }
}

// ---------------- loss + output assembly ----------------
__global__ void finalize_kernel(const float* __restrict__ logits, const int* __restrict__ labels,
                                const int* __restrict__ amask, float* __restrict__ out,
                                int out_size) {
    __shared__ float r1[256], r2[256];
    int tid = threadIdx.x;
    float ls = 0.f, ms = 0.f;
    for (int m = tid; m < Mm; m += 256) {
        const float* lr = logits + m * NCc;
        float mx = lr[0];
        #pragma unroll
        for (int c = 1; c < NCc; c++) mx = fmaxf(mx, lr[c]);
        float se = 0.f;
        #pragma unroll
        for (int c = 0; c < NCc; c++) se += expf(lr[c] - mx);
        float lse = logf(se) + mx;
        float nll = lse - lr[labels[m]];
        float mk = amask[m] ? 1.0f : 0.0f;
        ls += nll * mk;
        ms += mk;
    }
    r1[tid] = ls; r2[tid] = ms; __syncthreads();
    #pragma unroll
    for (int s = 128; s > 0; s >>= 1) {
        if (tid < s) { r1[tid] += r1[tid + s]; r2[tid] += r2[tid + s]; }
        __syncthreads();
    }
    float loss = r1[0] / fmaxf(r2[0], 1.0f);
    const int total = Mm * NCc;
    for (int i = tid; i < out_size; i += 256)
        out[i] = (i < total) ? logits[i] : loss;
}

// ---------------- host driver ----------------
extern "C" void kernel_launch(void* const* d_in, const int* in_sizes, int n_in,
                              void* d_out, int out_size) {
    const float* word_emb = (const float*)d_in[0];
    const float* emb_ln_s = (const float*)d_in[1];
    const float* emb_ln_b = (const float*)d_in[2];
    const float* rel_emb  = (const float*)d_in[3];
    const float* rel_ln_s = (const float*)d_in[4];
    const float* rel_ln_b = (const float*)d_in[5];
    const float* Wq = (const float*)d_in[6];
    const float* bq = (const float*)d_in[7];
    const float* Wk = (const float*)d_in[8];
    const float* bk = (const float*)d_in[9];
    const float* Wv = (const float*)d_in[10];
    const float* bv = (const float*)d_in[11];
    const float* Wo = (const float*)d_in[12];
    const float* bo = (const float*)d_in[13];
    const float* ln1_s = (const float*)d_in[14];
    const float* ln1_b = (const float*)d_in[15];
    const float* W1 = (const float*)d_in[16];
    const float* b1 = (const float*)d_in[17];
    const float* W2 = (const float*)d_in[18];
    const float* b2 = (const float*)d_in[19];
    const float* ln2_s = (const float*)d_in[20];
    const float* ln2_b = (const float*)d_in[21];
    const float* Wt = (const float*)d_in[22];
    const float* bt = (const float*)d_in[23];
    const float* tln_s = (const float*)d_in[24];
    const float* tln_b = (const float*)d_in[25];
    const float* Wd = (const float*)d_in[26];
    const float* bd = (const float*)d_in[27];
    const int* input_ids = (const int*)d_in[28];
    const int* amask     = (const int*)d_in[29];
    const int* labels    = (const int*)d_in[30];

    static bool init = false;
    static float *x, *sc, *c2p, *p2c, *tmp, *t, *part, *logits;
    static int *ic2p, *ip2c;
    static u16 *xhi,*xlo,*relhi,*rello,*qhi,*qlo,*khi,*klo,*vhi,*vlo;
    static u16 *pkhi,*pklo,*pqhi,*pqlo,*phi,*plo,*ctxhi,*ctxlo,*ffhi,*fflo;
    static u16 *wqhi,*wqlo,*wkhi,*wklo,*wvhi,*wvlo,*wohi,*wolo;
    static u16 *w1hi,*w1lo,*w2hi,*w2lo,*wthi,*wtlo;
    if (!init) {
        cudaGetSymbolAddress((void**)&x, g_x);
        cudaGetSymbolAddress((void**)&sc, g_sc);
        cudaGetSymbolAddress((void**)&c2p, g_c2p);
        cudaGetSymbolAddress((void**)&p2c, g_p2c);
        cudaGetSymbolAddress((void**)&tmp, g_tmp);
        cudaGetSymbolAddress((void**)&t, g_t);
        cudaGetSymbolAddress((void**)&part, g_part);
        cudaGetSymbolAddress((void**)&logits, g_logits);
        cudaGetSymbolAddress((void**)&ic2p, g_ic2p);
        cudaGetSymbolAddress((void**)&ip2c, g_ip2c);
        cudaGetSymbolAddress((void**)&xhi, g_xhi);   cudaGetSymbolAddress((void**)&xlo, g_xlo);
        cudaGetSymbolAddress((void**)&relhi, g_relhi); cudaGetSymbolAddress((void**)&rello, g_rello);
        cudaGetSymbolAddress((void**)&qhi, g_qhi);   cudaGetSymbolAddress((void**)&qlo, g_qlo);
        cudaGetSymbolAddress((void**)&khi, g_khi);   cudaGetSymbolAddress((void**)&klo, g_klo);
        cudaGetSymbolAddress((void**)&vhi, g_vhi);   cudaGetSymbolAddress((void**)&vlo, g_vlo);
        cudaGetSymbolAddress((void**)&pkhi, g_pkhi); cudaGetSymbolAddress((void**)&pklo, g_pklo);
        cudaGetSymbolAddress((void**)&pqhi, g_pqhi); cudaGetSymbolAddress((void**)&pqlo, g_pqlo);
        cudaGetSymbolAddress((void**)&phi, g_phi);   cudaGetSymbolAddress((void**)&plo, g_plo);
        cudaGetSymbolAddress((void**)&ctxhi, g_ctxhi); cudaGetSymbolAddress((void**)&ctxlo, g_ctxlo);
        cudaGetSymbolAddress((void**)&ffhi, g_ffhi); cudaGetSymbolAddress((void**)&fflo, g_fflo);
        cudaGetSymbolAddress((void**)&wqhi, g_wqhi); cudaGetSymbolAddress((void**)&wqlo, g_wqlo);
        cudaGetSymbolAddress((void**)&wkhi, g_wkhi); cudaGetSymbolAddress((void**)&wklo, g_wklo);
        cudaGetSymbolAddress((void**)&wvhi, g_wvhi); cudaGetSymbolAddress((void**)&wvlo, g_wvlo);
        cudaGetSymbolAddress((void**)&wohi, g_wohi); cudaGetSymbolAddress((void**)&wolo, g_wolo);
        cudaGetSymbolAddress((void**)&w1hi, g_w1hi); cudaGetSymbolAddress((void**)&w1lo, g_w1lo);
        cudaGetSymbolAddress((void**)&w2hi, g_w2hi); cudaGetSymbolAddress((void**)&w2lo, g_w2lo);
        cudaGetSymbolAddress((void**)&wthi, g_wthi); cudaGetSymbolAddress((void**)&wtlo, g_wtlo);
        init = true;
    }

    // ---- weight splitting (7 launches, all layers at once) ----
    {
        int n4hh = Ll * Hh * Hh / 4;             // 1M groups
        int n4ff = Ll * Hh * FFf / 4;            // 4M groups
        int n4t  = Hh * Hh / 4;
        wsplit_kernel<<<(n4hh + 255) / 256, 256>>>((const float4*)Wq, wqhi, wqlo, n4hh);
        wsplit_kernel<<<(n4hh + 255) / 256, 256>>>((const float4*)Wk, wkhi, wklo, n4hh);
        wsplit_kernel<<<(n4hh + 255) / 256, 256>>>((const float4*)Wv, wvhi, wvlo, n4hh);
        wsplit_kernel<<<(n4hh + 255) / 256, 256>>>((const float4*)Wo, wohi, wolo, n4hh);
        wsplit_kernel<<<(n4ff + 255) / 256, 256>>>((const float4*)W1, w1hi, w1lo, n4ff);
        wsplit_kernel<<<(n4ff + 255) / 256, 256>>>((const float4*)W2, w2hi, w2lo, n4ff);
        wsplit_kernel<<<(n4t  + 255) / 256, 256>>>((const float4*)Wt, wthi, wtlo, n4t);
    }

    // precompute
    idx_kernel<<<(Ss * Ss + 255) / 256, 256>>>(ic2p, ip2c);
    ln_split_kernel<<<Rr, 256>>>(rel_emb, rel_ln_s, rel_ln_b, relhi, rello);
    embed_kernel<<<Mm, 256>>>(word_emb, input_ids, amask, emb_ln_s, emb_ln_b, x, xhi, xlo);

    for (int l = 0; l < Ll; l++) {
        long wo_off = (long)l * Hh * Hh;
        long ff_off = (long)l * Hh * FFf;
        const float* bq_l = bq + l * Hh;
        const float* bk_l = bk + l * Hh;
        const float* bv_l = bv + l * Hh;
        const float* bo_l = bo + l * Hh;
        const float* b1_l = b1 + l * FFf;
        const float* b2_l = b2 + l * Hh;

        qkvpos_mma_b<<<dim3(8, 8, 5), 256>>>(
            xhi, xlo, relhi, rello,
            wqhi + wo_off, wqlo + wo_off, wkhi + wo_off, wklo + wo_off,
            wvhi + wo_off, wvlo + wo_off,
            bq_l, bk_l, bv_l,
            qhi, qlo, khi, klo, vhi, vlo, pkhi, pklo, pqhi, pqlo);

        att_mma_b<<<dim3(4, 4, 96), 256>>>(qhi, qlo, khi, klo, pkhi, pklo, pqhi, pqlo,
                                           sc, c2p, p2c);

        softmax_kernel<<<dim3(Ss, Bb * NHh), 256>>>(sc, c2p, p2c, ic2p, ip2c, amask, phi, plo);

        ctx_mma_b<<<dim3(1, 4, Bb * NHh), 256>>>(phi, plo, vhi, vlo, ctxhi, ctxlo);

        gemm_mma_split_b<<<dim3(8, 8, 4), 256>>>(ctxhi, ctxlo, wohi + wo_off, wolo + wo_off,
                                                 part, Hh, Hh, 4);
        reduce_bias_kernel<<<(Mm * Hh + 255) / 256, 256>>>(part, bo_l, tmp, Mm, Hh, 4, 0);
        add_ln_split_kernel<<<Mm, 256>>>(x, tmp, ln1_s + l * Hh, ln1_b + l * Hh, xhi, xlo);

        gemm_mma_b<<<dim3(32, 8), 256>>>(xhi, xlo, w1hi + ff_off, w1lo + ff_off,
                                         b1_l, ffhi, fflo, FFf, Hh, 1);
        gemm_mma_split_b<<<dim3(8, 8, 4), 256>>>(ffhi, fflo, w2hi + ff_off, w2lo + ff_off,
                                                 part, Hh, FFf, 4);
        reduce_bias_kernel<<<(Mm * Hh + 255) / 256, 256>>>(part, b2_l, tmp, Mm, Hh, 4, 0);
        add_ln_split_kernel<<<Mm, 256>>>(x, tmp, ln2_s + l * Hh, ln2_b + l * Hh, xhi, xlo);
    }

    // head: transform (GELU) split-K, LN, decoder
    gemm_mma_split_b<<<dim3(8, 8, 4), 256>>>(xhi, xlo, wthi, wtlo, part, Hh, Hh, 4);
    reduce_bias_kernel<<<(Mm * Hh + 255) / 256, 256>>>(part, bt, t, Mm, Hh, 4, 1);
    ln_kernel<<<Mm, 256>>>(t, t, tln_s, tln_b);
    gemm_bias_kernel<<<dim3((NCc + BN - 1) / BN, Mm / BM), 256>>>(t, Wd, bd, logits, Mm, NCc, Hh, 0);

    finalize_kernel<<<1, 256>>>(logits, labels, amask, (float*)d_out, out_size);
}

// round 16
// speedup vs baseline: 1.1933x; 1.1933x over previous
#include <cuda_runtime.h>
#include <cuda_bf16.h>
#include <math.h>

// ---------------- problem constants ----------------
#define Bb   2
#define Ss   512
#define Hh   1024
#define NHh  16
#define Dd   64
#define Ll   4
#define FFf  4096
#define Vv   12800
#define NCc  14
#define SPAN 256
#define Rr   512           // 2*SPAN
#define Mm   (Bb*Ss)       // 1024 tokens
#define EPSLN 1e-7f

typedef unsigned short u16;
typedef unsigned int   u32;

// ---------------- static device scratch (no allocation allowed) ----------------
__device__ float g_x   [Mm*Hh];
__device__ float g_rel [Rr*Hh];
__device__ float g_q   [Mm*Hh];
__device__ float g_k   [Mm*Hh];
__device__ float g_v   [Mm*Hh];
__device__ float g_posk[Rr*Hh];
__device__ float g_posq[Rr*Hh];
__device__ float g_sc  [(long)Bb*NHh*Ss*Ss];
__device__ float g_c2p [(long)Bb*NHh*Ss*Rr];
__device__ float g_p2c [(long)Bb*NHh*Ss*Rr];
__device__ float g_ctx [Mm*Hh];
__device__ float g_tmp [Mm*Hh];
__device__ float g_ff  [Mm*FFf];
__device__ float g_t   [Mm*Hh];
__device__ float g_part[4L*Mm*Hh];
__device__ float g_logits[Mm*NCc];
__device__ int   g_ic2p[Ss*Ss];
__device__ int   g_ip2c[Ss*Ss];

// ---------------- helpers ----------------
__device__ __forceinline__ float block_sum(float v, float* red) {
    int tid = threadIdx.x;
    red[tid] = v; __syncthreads();
    #pragma unroll
    for (int s = 128; s > 0; s >>= 1) {
        if (tid < s) red[tid] += red[tid + s];
        __syncthreads();
    }
    float r = red[0]; __syncthreads();
    return r;
}

__device__ __forceinline__ float gelu_exact(float x) {
    return 0.5f * x * (1.0f + erff(x * 0.70710678118654752f));
}

__device__ __forceinline__ void bfsplit(float x, u16& h, u16& l) {
    __nv_bfloat16 bh = __float2bfloat16_rn(x);
    float rem = x - __bfloat162float(bh);
    __nv_bfloat16 bl = __float2bfloat16_rn(rem);
    h = *(u16*)&bh;
    l = *(u16*)&bl;
}

__device__ __forceinline__ void mma16816(float* c,
                                         u32 a0, u32 a1, u32 a2, u32 a3,
                                         u32 b0, u32 b1) {
    asm volatile(
        "mma.sync.aligned.m16n8k16.row.col.f32.bf16.bf16.f32 "
        "{%0,%1,%2,%3},{%4,%5,%6,%7},{%8,%9},{%0,%1,%2,%3};\n"
        : "+f"(c[0]), "+f"(c[1]), "+f"(c[2]), "+f"(c[3])
        : "r"(a0), "r"(a1), "r"(a2), "r"(a3), "r"(b0), "r"(b1));
}

// ================= smem tile structs (one buffer; двух-buffer via dynamic smem) ====
struct SmemNN {
    u16 Ahi[128][40]; u16 Alo[128][40];
    u16 Bhi[32][136]; u16 Blo[32][136];
};
struct SmemNT {
    u16 Ahi[128][40]; u16 Alo[128][40];
    u16 Bhi[128][40]; u16 Blo[128][40];
};
struct SmemCtx {
    u16 Ahi[128][40]; u16 Alo[128][40];
    u16 Bhi[64][40];  u16 Blo[64][40];
};

// ---- loader: 128 rows x 32 k fp32 -> split -> [rows][40]-padded smem ----
__device__ __forceinline__ void load_rows_f32(
    u16 (*dhi)[40], u16 (*dlo)[40],
    const float* __restrict__ A, int lda, int row0, int k0) {
    int tid = threadIdx.x;
    #pragma unroll
    for (int i = 0; i < 4; i++) {
        int idx = i * 256 + tid;
        int m = idx >> 3, kq = (idx & 7) * 4;
        float4 av = *(const float4*)(A + (long)(row0 + m) * lda + k0 + kq);
        u16 h0,h1,h2,h3,l0,l1,l2,l3;
        bfsplit(av.x,h0,l0); bfsplit(av.y,h1,l1);
        bfsplit(av.z,h2,l2); bfsplit(av.w,h3,l3);
        *(u32*)&dhi[m][kq]   = (u32)h0 | ((u32)h1 << 16);
        *(u32*)&dhi[m][kq+2] = (u32)h2 | ((u32)h3 << 16);
        *(u32*)&dlo[m][kq]   = (u32)l0 | ((u32)l1 << 16);
        *(u32*)&dlo[m][kq+2] = (u32)l2 | ((u32)l3 << 16);
    }
}

// ---- loader: 32 k x 128 n (k-major weights) -> [32][136]-padded smem ----
__device__ __forceinline__ void load_b_nn_f32(
    u16 (*dhi)[136], u16 (*dlo)[136],
    const float* __restrict__ W, int N, int k0, int col0) {
    int tid = threadIdx.x;
    #pragma unroll
    for (int i = 0; i < 4; i++) {
        int idx = i * 256 + tid;
        int kk = idx >> 5, n4 = (idx & 31) * 4;
        float4 wv = *(const float4*)(W + (long)(k0 + kk) * N + col0 + n4);
        u16 h0,h1,h2,h3,l0,l1,l2,l3;
        bfsplit(wv.x,h0,l0); bfsplit(wv.y,h1,l1);
        bfsplit(wv.z,h2,l2); bfsplit(wv.w,h3,l3);
        *(u32*)&dhi[kk][n4]   = (u32)h0 | ((u32)h1 << 16);
        *(u32*)&dhi[kk][n4+2] = (u32)h2 | ((u32)h3 << 16);
        *(u32*)&dlo[kk][n4]   = (u32)l0 | ((u32)l1 << 16);
        *(u32*)&dlo[kk][n4+2] = (u32)l2 | ((u32)l3 << 16);
    }
}

// ---- compute: NN (B gathered from k-major smem) ----
__device__ __forceinline__ void mma_compute_nn(SmemNN& sm, float acc[64],
                                               int wm, int wn, int gg, int qq) {
    #pragma unroll
    for (int ks = 0; ks < 32; ks += 16) {
        u32 ah[2][4], al[2][4];
        #pragma unroll
        for (int mt = 0; mt < 2; mt++) {
            int r  = wm * 32 + mt * 16 + gg;
            int kc = ks + 2 * qq;
            ah[mt][0] = *(u32*)&sm.Ahi[r    ][kc    ];
            ah[mt][1] = *(u32*)&sm.Ahi[r + 8][kc    ];
            ah[mt][2] = *(u32*)&sm.Ahi[r    ][kc + 8];
            ah[mt][3] = *(u32*)&sm.Ahi[r + 8][kc + 8];
            al[mt][0] = *(u32*)&sm.Alo[r    ][kc    ];
            al[mt][1] = *(u32*)&sm.Alo[r + 8][kc    ];
            al[mt][2] = *(u32*)&sm.Alo[r    ][kc + 8];
            al[mt][3] = *(u32*)&sm.Alo[r + 8][kc + 8];
        }
        #pragma unroll
        for (int nt = 0; nt < 8; nt++) {
            int n  = wn * 64 + nt * 8 + gg;
            int kb = ks + 2 * qq;
            u32 bh0 = (u32)sm.Bhi[kb    ][n] | ((u32)sm.Bhi[kb + 1][n] << 16);
            u32 bh1 = (u32)sm.Bhi[kb + 8][n] | ((u32)sm.Bhi[kb + 9][n] << 16);
            u32 bl0 = (u32)sm.Blo[kb    ][n] | ((u32)sm.Blo[kb + 1][n] << 16);
            u32 bl1 = (u32)sm.Blo[kb + 8][n] | ((u32)sm.Blo[kb + 9][n] << 16);
            #pragma unroll
            for (int mt = 0; mt < 2; mt++) {
                float* c = acc + (mt * 8 + nt) * 4;
                mma16816(c, ah[mt][0], ah[mt][1], ah[mt][2], ah[mt][3], bh0, bh1);
                mma16816(c, ah[mt][0], ah[mt][1], ah[mt][2], ah[mt][3], bl0, bl1);
                mma16816(c, al[mt][0], al[mt][1], al[mt][2], al[mt][3], bh0, bh1);
            }
        }
    }
}

// ---- compute: NT (B aligned from [n][40] smem) ----
__device__ __forceinline__ void mma_compute_nt(SmemNT& sm, float acc[64],
                                               int wm, int wn, int gg, int qq) {
    #pragma unroll
    for (int ks = 0; ks < 32; ks += 16) {
        u32 ah[2][4], al[2][4];
        #pragma unroll
        for (int mt = 0; mt < 2; mt++) {
            int r  = wm * 32 + mt * 16 + gg;
            int kc = ks + 2 * qq;
            ah[mt][0] = *(u32*)&sm.Ahi[r    ][kc    ];
            ah[mt][1] = *(u32*)&sm.Ahi[r + 8][kc    ];
            ah[mt][2] = *(u32*)&sm.Ahi[r    ][kc + 8];
            ah[mt][3] = *(u32*)&sm.Ahi[r + 8][kc + 8];
            al[mt][0] = *(u32*)&sm.Alo[r    ][kc    ];
            al[mt][1] = *(u32*)&sm.Alo[r + 8][kc    ];
            al[mt][2] = *(u32*)&sm.Alo[r    ][kc + 8];
            al[mt][3] = *(u32*)&sm.Alo[r + 8][kc + 8];
        }
        #pragma unroll
        for (int nt = 0; nt < 8; nt++) {
            int n  = wn * 64 + nt * 8 + gg;
            int kb = ks + 2 * qq;
            u32 bh0 = *(u32*)&sm.Bhi[n][kb];
            u32 bh1 = *(u32*)&sm.Bhi[n][kb + 8];
            u32 bl0 = *(u32*)&sm.Blo[n][kb];
            u32 bl1 = *(u32*)&sm.Blo[n][kb + 8];
            #pragma unroll
            for (int mt = 0; mt < 2; mt++) {
                float* c = acc + (mt * 8 + nt) * 4;
                mma16816(c, ah[mt][0], ah[mt][1], ah[mt][2], ah[mt][3], bh0, bh1);
                mma16816(c, ah[mt][0], ah[mt][1], ah[mt][2], ah[mt][3], bl0, bl1);
                mma16816(c, al[mt][0], al[mt][1], al[mt][2], al[mt][3], bh0, bh1);
            }
        }
    }
}

// ---- epilogues (fp32 outputs) ----
__device__ void mma_epi_bias(float* __restrict__ C, const float* __restrict__ bias,
                             float acc[64], int row0, int col0, int ldc, int act) {
    int tid = threadIdx.x, lane = tid & 31, warp = tid >> 5;
    int wm = warp & 3, wn = warp >> 2;
    int gg = lane >> 2, qq = lane & 3;
    #pragma unroll
    for (int mt = 0; mt < 2; mt++)
        #pragma unroll
        for (int nt = 0; nt < 8; nt++) {
            int row = row0 + wm * 32 + mt * 16 + gg;
            int col = col0 + wn * 64 + nt * 8 + 2 * qq;
            const float* c = acc + (mt * 8 + nt) * 4;
            float2 v0 = { c[0] + bias[col], c[1] + bias[col + 1] };
            float2 v1 = { c[2] + bias[col], c[3] + bias[col + 1] };
            if (act) {
                v0.x = gelu_exact(v0.x); v0.y = gelu_exact(v0.y);
                v1.x = gelu_exact(v1.x); v1.y = gelu_exact(v1.y);
            }
            *(float2*)(C + (long)row * ldc + col)       = v0;
            *(float2*)(C + (long)(row + 8) * ldc + col) = v1;
        }
}

__device__ void mma_epi_raw(float* __restrict__ C, float acc[64],
                            int row0, int col0, int ldc) {
    int tid = threadIdx.x, lane = tid & 31, warp = tid >> 5;
    int wm = warp & 3, wn = warp >> 2;
    int gg = lane >> 2, qq = lane & 3;
    #pragma unroll
    for (int mt = 0; mt < 2; mt++)
        #pragma unroll
        for (int nt = 0; nt < 8; nt++) {
            int row = row0 + wm * 32 + mt * 16 + gg;
            int col = col0 + wn * 64 + nt * 8 + 2 * qq;
            const float* c = acc + (mt * 8 + nt) * 4;
            *(float2*)(C + (long)row * ldc + col)       = make_float2(c[0], c[1]);
            *(float2*)(C + (long)(row + 8) * ldc + col) = make_float2(c[2], c[3]);
        }
}

// ================= kernels (double-buffered, one sync per k-chunk) =================

// fused q/k/v + pos_k/pos_q projections (z=0..4)
__global__ __launch_bounds__(256, 2) void qkvpos_mma(
    const float* __restrict__ x, const float* __restrict__ rel,
    const float* __restrict__ Wq, const float* __restrict__ Wk, const float* __restrict__ Wv,
    const float* __restrict__ bq, const float* __restrict__ bk, const float* __restrict__ bv,
    float* q, float* k, float* v, float* posk, float* posq) {
    extern __shared__ char smraw[];
    SmemNN* bufs = (SmemNN*)smraw;
    int z = blockIdx.z;
    const float *A, *W, *bias; float* C;
    if (z == 0)      { A = x;   W = Wq; bias = bq; C = q; }
    else if (z == 1) { A = x;   W = Wk; bias = bk; C = k; }
    else if (z == 2) { A = x;   W = Wv; bias = bv; C = v; }
    else if (z == 3) { if (blockIdx.y >= 4) return; A = rel; W = Wk; bias = bk; C = posk; }
    else             { if (blockIdx.y >= 4) return; A = rel; W = Wq; bias = bq; C = posq; }
    int tid = threadIdx.x, lane = tid & 31, warp = tid >> 5;
    int wm = warp & 3, wn = warp >> 2, gg = lane >> 2, qq = lane & 3;
    int row0 = blockIdx.y * 128, col0 = blockIdx.x * 128;
    float acc[64] = {};
    load_rows_f32(bufs[0].Ahi, bufs[0].Alo, A, Hh, row0, 0);
    load_b_nn_f32(bufs[0].Bhi, bufs[0].Blo, W, Hh, 0, col0);
    __syncthreads();
    int cur = 0;
    for (int k0 = 0; k0 < Hh; k0 += 32) {
        int kn = k0 + 32;
        if (kn < Hh) {
            load_rows_f32(bufs[cur ^ 1].Ahi, bufs[cur ^ 1].Alo, A, Hh, row0, kn);
            load_b_nn_f32(bufs[cur ^ 1].Bhi, bufs[cur ^ 1].Blo, W, Hh, kn, col0);
        }
        mma_compute_nn(bufs[cur], acc, wm, wn, gg, qq);
        __syncthreads();
        cur ^= 1;
    }
    mma_epi_bias(C, bias, acc, row0, col0, Hh, 0);
}

// generic NN GEMM with bias (+GELU)  (FFN1)
__global__ __launch_bounds__(256, 2) void gemm_mma(
    const float* __restrict__ A, const float* __restrict__ W,
    const float* __restrict__ bias, float* C, int N, int K, int act) {
    extern __shared__ char smraw[];
    SmemNN* bufs = (SmemNN*)smraw;
    int tid = threadIdx.x, lane = tid & 31, warp = tid >> 5;
    int wm = warp & 3, wn = warp >> 2, gg = lane >> 2, qq = lane & 3;
    int row0 = blockIdx.y * 128, col0 = blockIdx.x * 128;
    float acc[64] = {};
    load_rows_f32(bufs[0].Ahi, bufs[0].Alo, A, K, row0, 0);
    load_b_nn_f32(bufs[0].Bhi, bufs[0].Blo, W, N, 0, col0);
    __syncthreads();
    int cur = 0;
    for (int k0 = 0; k0 < K; k0 += 32) {
        int kn = k0 + 32;
        if (kn < K) {
            load_rows_f32(bufs[cur ^ 1].Ahi, bufs[cur ^ 1].Alo, A, K, row0, kn);
            load_b_nn_f32(bufs[cur ^ 1].Bhi, bufs[cur ^ 1].Blo, W, N, kn, col0);
        }
        mma_compute_nn(bufs[cur], acc, wm, wn, gg, qq);
        __syncthreads();
        cur ^= 1;
    }
    mma_epi_bias(C, bias, acc, row0, col0, N, act);
}

// split-K NN GEMM -> fp32 partials (deterministic; z = k-chunk)
__global__ __launch_bounds__(256, 2) void gemm_mma_split(
    const float* __restrict__ A, const float* __restrict__ W,
    float* P, int N, int K, int nsplit) {
    extern __shared__ char smraw[];
    SmemNN* bufs = (SmemNN*)smraw;
    int z = blockIdx.z;
    int kc = K / nsplit;
    int kstart = z * kc, kend = kstart + kc;
    int tid = threadIdx.x, lane = tid & 31, warp = tid >> 5;
    int wm = warp & 3, wn = warp >> 2, gg = lane >> 2, qq = lane & 3;
    int row0 = blockIdx.y * 128, col0 = blockIdx.x * 128;
    float acc[64] = {};
    load_rows_f32(bufs[0].Ahi, bufs[0].Alo, A, K, row0, kstart);
    load_b_nn_f32(bufs[0].Bhi, bufs[0].Blo, W, N, kstart, col0);
    __syncthreads();
    int cur = 0;
    for (int k0 = kstart; k0 < kend; k0 += 32) {
        int kn = k0 + 32;
        if (kn < kend) {
            load_rows_f32(bufs[cur ^ 1].Ahi, bufs[cur ^ 1].Alo, A, K, row0, kn);
            load_b_nn_f32(bufs[cur ^ 1].Bhi, bufs[cur ^ 1].Blo, W, N, kn, col0);
        }
        mma_compute_nn(bufs[cur], acc, wm, wn, gg, qq);
        __syncthreads();
        cur ^= 1;
    }
    int M = gridDim.y * 128;
    mma_epi_raw(P + (long)z * M * N, acc, row0, col0, N);
}

__global__ void reduce_bias_kernel(const float* __restrict__ P, const float* __restrict__ bias,
                                   float* __restrict__ C, int M, int N, int nsplit, int act) {
    int i = blockIdx.x * blockDim.x + threadIdx.x;
    long sz = (long)M * N;
    if (i >= sz) return;
    float s = 0.f;
    for (int p = 0; p < nsplit; p++) s += P[(long)p * sz + i];
    s += bias[i & (N - 1)];
    if (act) s = gelu_exact(s);
    C[i] = s;
}

// fused scores / c2p / p2c NT batched GEMM (z = type*32 + bh)
__global__ __launch_bounds__(256, 2) void att_mma_kernel(
    const float* __restrict__ q, const float* __restrict__ k,
    const float* __restrict__ posk, const float* __restrict__ posq,
    float* sc, float* c2p, float* p2c) {
    extern __shared__ char smraw[];
    SmemNT* bufs = (SmemNT*)smraw;
    int z = blockIdx.z;
    int type = z >> 5;
    int bh = z & 31;
    int b = bh >> 4, h = bh & 15;
    const float* A = ((type == 2) ? k : q) + (long)b * Ss * Hh + (long)h * Dd;
    const float* B;
    if (type == 0)      B = k    + (long)b * Ss * Hh + (long)h * Dd;
    else if (type == 1) B = posk + (long)h * Dd;
    else                B = posq + (long)h * Dd;
    float* C = (type == 0 ? sc : (type == 1 ? c2p : p2c)) + (long)bh * Ss * 512;
    int tid = threadIdx.x, lane = tid & 31, warp = tid >> 5;
    int wm = warp & 3, wn = warp >> 2, gg = lane >> 2, qq = lane & 3;
    int row0 = blockIdx.y * 128, col0 = blockIdx.x * 128;
    float acc[64] = {};
    load_rows_f32(bufs[0].Ahi, bufs[0].Alo, A, Hh, row0, 0);
    load_rows_f32(bufs[0].Bhi, bufs[0].Blo, B, Hh, col0, 0);
    __syncthreads();
    int cur = 0;
    #pragma unroll
    for (int k0 = 0; k0 < Dd; k0 += 32) {
        int kn = k0 + 32;
        if (kn < Dd) {
            load_rows_f32(bufs[cur ^ 1].Ahi, bufs[cur ^ 1].Alo, A, Hh, row0, kn);
            load_rows_f32(bufs[cur ^ 1].Bhi, bufs[cur ^ 1].Blo, B, Hh, col0, kn);
        }
        mma_compute_nt(bufs[cur], acc, wm, wn, gg, qq);
        __syncthreads();
        cur ^= 1;
    }
    mma_epi_raw(C, acc, row0, col0, 512);
}

// ctx = probs @ v (K=512, N=64)
__global__ __launch_bounds__(256, 2) void ctx_mma_kernel(
    const float* __restrict__ sc, const float* __restrict__ v, float* __restrict__ ctx) {
    extern __shared__ char smraw[];
    SmemCtx* bufs = (SmemCtx*)smraw;
    int bh = blockIdx.z;
    int b = bh >> 4, h = bh & 15;
    const float* A = sc + (long)bh * Ss * Ss;
    const float* Bv = v + (long)b * Ss * Hh + (long)h * Dd;
    float* C = ctx + (long)b * Ss * Hh + (long)h * Dd;
    int tid = threadIdx.x, lane = tid & 31, warp = tid >> 5;
    int wm = warp & 3, wn = warp >> 2, gg = lane >> 2, qq = lane & 3;
    int row0 = blockIdx.y * 128;
    float acc[32] = {};

    // B loader lambda-style (32 s-rows x 64 d -> transposed [d][s])
    auto load_bv = [&](SmemCtx& sm, int k0) {
        #pragma unroll
        for (int i = 0; i < 2; i++) {
            int idx = i * 256 + tid;
            int kk = idx >> 4, n4 = (idx & 15) * 4;
            float4 bvv = *(const float4*)(Bv + (long)(k0 + kk) * Hh + n4);
            u16 h0,h1,h2,h3,l0,l1,l2,l3;
            bfsplit(bvv.x,h0,l0); bfsplit(bvv.y,h1,l1);
            bfsplit(bvv.z,h2,l2); bfsplit(bvv.w,h3,l3);
            sm.Bhi[n4+0][kk] = h0; sm.Bhi[n4+1][kk] = h1;
            sm.Bhi[n4+2][kk] = h2; sm.Bhi[n4+3][kk] = h3;
            sm.Blo[n4+0][kk] = l0; sm.Blo[n4+1][kk] = l1;
            sm.Blo[n4+2][kk] = l2; sm.Blo[n4+3][kk] = l3;
        }
    };

    load_rows_f32(bufs[0].Ahi, bufs[0].Alo, A, Ss, row0, 0);
    load_bv(bufs[0], 0);
    __syncthreads();
    int cur = 0;
    for (int k0 = 0; k0 < Ss; k0 += 32) {
        int kn = k0 + 32;
        if (kn < Ss) {
            load_rows_f32(bufs[cur ^ 1].Ahi, bufs[cur ^ 1].Alo, A, Ss, row0, kn);
            load_bv(bufs[cur ^ 1], kn);
        }
        SmemCtx& sm = bufs[cur];
        #pragma unroll
        for (int ks = 0; ks < 32; ks += 16) {
            u32 ah[2][4], al[2][4];
            #pragma unroll
            for (int mt = 0; mt < 2; mt++) {
                int r  = wm * 32 + mt * 16 + gg;
                int kc = ks + 2 * qq;
                ah[mt][0] = *(u32*)&sm.Ahi[r    ][kc    ];
                ah[mt][1] = *(u32*)&sm.Ahi[r + 8][kc    ];
                ah[mt][2] = *(u32*)&sm.Ahi[r    ][kc + 8];
                ah[mt][3] = *(u32*)&sm.Ahi[r + 8][kc + 8];
                al[mt][0] = *(u32*)&sm.Alo[r    ][kc    ];
                al[mt][1] = *(u32*)&sm.Alo[r + 8][kc    ];
                al[mt][2] = *(u32*)&sm.Alo[r    ][kc + 8];
                al[mt][3] = *(u32*)&sm.Alo[r + 8][kc + 8];
            }
            #pragma unroll
            for (int nt = 0; nt < 4; nt++) {
                int n  = wn * 32 + nt * 8 + gg;
                int kb = ks + 2 * qq;
                u32 bh0 = *(u32*)&sm.Bhi[n][kb];
                u32 bh1 = *(u32*)&sm.Bhi[n][kb + 8];
                u32 bl0 = *(u32*)&sm.Blo[n][kb];
                u32 bl1 = *(u32*)&sm.Blo[n][kb + 8];
                #pragma unroll
                for (int mt = 0; mt < 2; mt++) {
                    float* c = acc + (mt * 4 + nt) * 4;
                    mma16816(c, ah[mt][0], ah[mt][1], ah[mt][2], ah[mt][3], bh0, bh1);
                    mma16816(c, ah[mt][0], ah[mt][1], ah[mt][2], ah[mt][3], bl0, bl1);
                    mma16816(c, al[mt][0], al[mt][1], al[mt][2], al[mt][3], bh0, bh1);
                }
            }
        }
        __syncthreads();
        cur ^= 1;
    }

    #pragma unroll
    for (int mt = 0; mt < 2; mt++)
        #pragma unroll
        for (int nt = 0; nt < 4; nt++) {
            int row = row0 + wm * 32 + mt * 16 + gg;
            int col = wn * 32 + nt * 8 + 2 * qq;
            const float* c = acc + (mt * 4 + nt) * 4;
            *(float2*)(C + (long)row * Hh + col)       = make_float2(c[0], c[1]);
            *(float2*)(C + (long)(row + 8) * Hh + col) = make_float2(c[2], c[3]);
        }
}

// ---------------- relative-position bucket indices ----------------
__global__ void idx_kernel(int* c2pidx, int* p2cidx) {
    int t = blockIdx.x * blockDim.x + threadIdx.x;
    if (t >= Ss * Ss) return;
    int q = t / Ss, k = t % Ss;
    int rel = q - k;
    const int mid = 128;
    int ap = (rel < mid && rel > -mid) ? (mid - 1) : (rel < 0 ? -rel : rel);
    int bucket;
    if (ap <= mid) {
        bucket = rel;
    } else {
        const float divisor = (float)1.3843393288235763;  // np.log(511/128) as f32
        float lp = ceilf(logf((float)ap / 128.0f) / divisor * 127.0f) + 128.0f;
        float sgn = (rel > 0) ? 1.0f : ((rel < 0) ? -1.0f : 0.0f);
        bucket = (int)(lp * sgn);
    }
    int c = bucket + SPAN;  c = c < 0 ? 0 : (c > 2 * SPAN - 1 ? 2 * SPAN - 1 : c);
    int p = -bucket + SPAN; p = p < 0 ? 0 : (p > 2 * SPAN - 1 ? 2 * SPAN - 1 : p);
    c2pidx[t] = c;
    p2cidx[t] = p;
}

// ---------------- embedding: x = LN(word_emb[ids]) * mask ----------------
__global__ void embed_kernel(const float* __restrict__ wemb, const int* __restrict__ ids,
                             const int* __restrict__ amask,
                             const float* __restrict__ s, const float* __restrict__ bb,
                             float* __restrict__ out) {
    __shared__ float red[256];
    int m = blockIdx.x, tid = threadIdx.x;
    const float* in = wemb + (long)ids[m] * Hh;
    float v[4];
    #pragma unroll
    for (int i = 0; i < 4; i++) v[i] = in[tid + i * 256];
    float sum = 0.f;
    #pragma unroll
    for (int i = 0; i < 4; i++) sum += v[i];
    float mu = block_sum(sum, red) * (1.0f / Hh);
    float var = 0.f;
    #pragma unroll
    for (int i = 0; i < 4; i++) { float d = v[i] - mu; var += d * d; }
    float vt = block_sum(var, red) * (1.0f / Hh);
    float inv = rsqrtf(vt + EPSLN);
    float mk = amask[m] ? 1.0f : 0.0f;
    #pragma unroll
    for (int i = 0; i < 4; i++) {
        int c = tid + i * 256;
        out[(long)m * Hh + c] = ((v[i] - mu) * inv * s[c] + bb[c]) * mk;
    }
}

// ---------------- plain row LayerNorm over H=1024 ----------------
__global__ void ln_kernel(const float* __restrict__ in, float* __restrict__ out,
                          const float* __restrict__ s, const float* __restrict__ bb) {
    __shared__ float red[256];
    int m = blockIdx.x, tid = threadIdx.x;
    const float* ir = in + (long)m * Hh;
    float v[4];
    #pragma unroll
    for (int i = 0; i < 4; i++) v[i] = ir[tid + i * 256];
    float sum = 0.f;
    #pragma unroll
    for (int i = 0; i < 4; i++) sum += v[i];
    float mu = block_sum(sum, red) * (1.0f / Hh);
    float var = 0.f;
    #pragma unroll
    for (int i = 0; i < 4; i++) { float d = v[i] - mu; var += d * d; }
    float vt = block_sum(var, red) * (1.0f / Hh);
    float inv = rsqrtf(vt + EPSLN);
    #pragma unroll
    for (int i = 0; i < 4; i++) {
        int c = tid + i * 256;
        out[(long)m * Hh + c] = (v[i] - mu) * inv * s[c] + bb[c];
    }
}

// ---------------- residual + LayerNorm: h = LN(h + y) ----------------
__global__ void add_ln_kernel(float* __restrict__ h, const float* __restrict__ y,
                              const float* __restrict__ s, const float* __restrict__ bb) {
    __shared__ float red[256];
    int m = blockIdx.x, tid = threadIdx.x;
    long base = (long)m * Hh;
    float v[4];
    #pragma unroll
    for (int i = 0; i < 4; i++) { int c = tid + i * 256; v[i] = h[base + c] + y[base + c]; }
    float sum = 0.f;
    #pragma unroll
    for (int i = 0; i < 4; i++) sum += v[i];
    float mu = block_sum(sum, red) * (1.0f / Hh);
    float var = 0.f;
    #pragma unroll
    for (int i = 0; i < 4; i++) { float d = v[i] - mu; var += d * d; }
    float vt = block_sum(var, red) * (1.0f / Hh);
    float inv = rsqrtf(vt + EPSLN);
    #pragma unroll
    for (int i = 0; i < 4; i++) {
        int c = tid + i * 256;
        h[base + c] = (v[i] - mu) * inv * s[c] + bb[c];
    }
}

// ---------------- small-N SGEMM (decoder head, N=14) ----------------
#define BM 64
#define BN 64
#define BK 16
__global__ void gemm_bias_kernel(const float* __restrict__ A, const float* __restrict__ W,
                                 const float* __restrict__ bias, float* __restrict__ C,
                                 int M, int N, int K, int act) {
    __shared__ float As[BK][BM];
    __shared__ float Bs[BK][BN];
    int tid = threadIdx.x;
    int tx = tid & 15, ty = tid >> 4;
    int row0 = blockIdx.y * BM, col0 = blockIdx.x * BN;
    float acc[4][4] = {};
    for (int k0 = 0; k0 < K; k0 += BK) {
        #pragma unroll
        for (int i = 0; i < 4; i++) {
            int idx = tid + i * 256;
            int kk = idx >> 6, mm = idx & 63;
            As[kk][mm] = A[(long)(row0 + mm) * K + k0 + kk];
        }
        #pragma unroll
        for (int i = 0; i < 4; i++) {
            int idx = tid + i * 256;
            int kk = idx >> 6, nn = idx & 63;
            int col = col0 + nn;
            Bs[kk][nn] = (col < N) ? W[(long)(k0 + kk) * N + col] : 0.0f;
        }
        __syncthreads();
        #pragma unroll
        for (int kk = 0; kk < BK; kk++) {
            float a[4], b[4];
            #pragma unroll
            for (int i = 0; i < 4; i++) a[i] = As[kk][ty * 4 + i];
            #pragma unroll
            for (int j = 0; j < 4; j++) b[j] = Bs[kk][tx * 4 + j];
            #pragma unroll
            for (int i = 0; i < 4; i++)
                #pragma unroll
                for (int j = 0; j < 4; j++)
                    acc[i][j] += a[i] * b[j];
        }
        __syncthreads();
    }
    #pragma unroll
    for (int i = 0; i < 4; i++) {
        int r = row0 + ty * 4 + i;
        #pragma unroll
        for (int j = 0; j < 4; j++) {
            int c = col0 + tx * 4 + j;
            if (c < N) {
                float v = acc[i][j] + bias[c];
                if (act == 1) v = gelu_exact(v);
                C[(long)r * N + c] = v;
            }
        }
    }
}

// ---------------- fused gather + scale + mask + softmax (in place) ----
__global__ void softmax_kernel(float* __restrict__ scores,
                               const float* __restrict__ c2p, const float* __restrict__ p2c,
                               const int* __restrict__ ic2p, const int* __restrict__ ip2c,
                               const int* __restrict__ amask) {
    __shared__ float sm[Ss];
    __shared__ float red[256];
    int q  = blockIdx.x;
    int bh = blockIdx.y;
    int b  = bh / NHh;
    int tid = threadIdx.x;
    const float inv_scale = 0.07216878364870322f;  // 1/sqrt(3*D)
    int maskq = amask[b * Ss + q];
    float* row = scores + ((long)bh * Ss + q) * Ss;
    const float* c2pr = c2p + ((long)bh * Ss + q) * Rr;
    const float* p2cb = p2c + (long)bh * Ss * Rr;

    for (int k = tid; k < Ss; k += 256) {
        float s;
        if (maskq && amask[b * Ss + k]) {
            s = (row[k] + c2pr[ic2p[q * Ss + k]] + p2cb[(long)k * Rr + ip2c[k * Ss + q]]) * inv_scale;
        } else {
            s = -INFINITY;
        }
        sm[k] = s;
    }
    __syncthreads();
    float mx = -INFINITY;
    for (int k = tid; k < Ss; k += 256) mx = fmaxf(mx, sm[k]);
    red[tid] = mx; __syncthreads();
    #pragma unroll
    for (int s = 128; s > 0; s >>= 1) {
        if (tid < s) red[tid] = fmaxf(red[tid], red[tid + s]);
        __syncthreads();
    }
    mx = red[0]; __syncthreads();
    if (mx == -INFINITY) {
        for (int k = tid; k < Ss; k += 256) row[k] = 0.0f;
        return;
    }
    float sum = 0.f;
    for (int k = tid; k < Ss; k += 256) {
        float e = expf(sm[k] - mx);
        sm[k] = e;
        sum += e;
    }
    float tot = block_sum(sum, red);
    float inv = 1.0f / tot;
    for (int k = tid; k < Ss; k += 256) row[k] = sm[k] * inv;
}

// ---------------- loss + output assembly ----------------
__global__ void finalize_kernel(const float* __restrict__ logits, const int* __restrict__ labels,
                                const int* __restrict__ amask, float* __restrict__ out,
                                int out_size) {
    __shared__ float r1[256], r2[256];
    int tid = threadIdx.x;
    float ls = 0.f, ms = 0.f;
    for (int m = tid; m < Mm; m += 256) {
        const float* lr = logits + m * NCc;
        float mx = lr[0];
        #pragma unroll
        for (int c = 1; c < NCc; c++) mx = fmaxf(mx, lr[c]);
        float se = 0.f;
        #pragma unroll
        for (int c = 0; c < NCc; c++) se += expf(lr[c] - mx);
        float lse = logf(se) + mx;
        float nll = lse - lr[labels[m]];
        float mk = amask[m] ? 1.0f : 0.0f;
        ls += nll * mk;
        ms += mk;
    }
    r1[tid] = ls; r2[tid] = ms; __syncthreads();
    #pragma unroll
    for (int s = 128; s > 0; s >>= 1) {
        if (tid < s) { r1[tid] += r1[tid + s]; r2[tid] += r2[tid + s]; }
        __syncthreads();
    }
    float loss = r1[0] / fmaxf(r2[0], 1.0f);
    const int total = Mm * NCc;
    for (int i = tid; i < out_size; i += 256)
        out[i] = (i < total) ? logits[i] : loss;
}

// ---------------- host driver ----------------
extern "C" void kernel_launch(void* const* d_in, const int* in_sizes, int n_in,
                              void* d_out, int out_size) {
    const float* word_emb = (const float*)d_in[0];
    const float* emb_ln_s = (const float*)d_in[1];
    const float* emb_ln_b = (const float*)d_in[2];
    const float* rel_emb  = (const float*)d_in[3];
    const float* rel_ln_s = (const float*)d_in[4];
    const float* rel_ln_b = (const float*)d_in[5];
    const float* Wq = (const float*)d_in[6];
    const float* bq = (const float*)d_in[7];
    const float* Wk = (const float*)d_in[8];
    const float* bk = (const float*)d_in[9];
    const float* Wv = (const float*)d_in[10];
    const float* bv = (const float*)d_in[11];
    const float* Wo = (const float*)d_in[12];
    const float* bo = (const float*)d_in[13];
    const float* ln1_s = (const float*)d_in[14];
    const float* ln1_b = (const float*)d_in[15];
    const float* W1 = (const float*)d_in[16];
    const float* b1 = (const float*)d_in[17];
    const float* W2 = (const float*)d_in[18];
    const float* b2 = (const float*)d_in[19];
    const float* ln2_s = (const float*)d_in[20];
    const float* ln2_b = (const float*)d_in[21];
    const float* Wt = (const float*)d_in[22];
    const float* bt = (const float*)d_in[23];
    const float* tln_s = (const float*)d_in[24];
    const float* tln_b = (const float*)d_in[25];
    const float* Wd = (const float*)d_in[26];
    const float* bd = (const float*)d_in[27];
    const int* input_ids = (const int*)d_in[28];
    const int* amask     = (const int*)d_in[29];
    const int* labels    = (const int*)d_in[30];

    static bool init = false;
    static float *x, *rel, *q, *k, *v, *posk, *posq, *sc, *c2p, *p2c, *ctx, *tmp, *ff, *t, *part, *logits;
    static int *ic2p, *ip2c;
    if (!init) {
        cudaGetSymbolAddress((void**)&x, g_x);
        cudaGetSymbolAddress((void**)&rel, g_rel);
        cudaGetSymbolAddress((void**)&q, g_q);
        cudaGetSymbolAddress((void**)&k, g_k);
        cudaGetSymbolAddress((void**)&v, g_v);
        cudaGetSymbolAddress((void**)&posk, g_posk);
        cudaGetSymbolAddress((void**)&posq, g_posq);
        cudaGetSymbolAddress((void**)&sc, g_sc);
        cudaGetSymbolAddress((void**)&c2p, g_c2p);
        cudaGetSymbolAddress((void**)&p2c, g_p2c);
        cudaGetSymbolAddress((void**)&ctx, g_ctx);
        cudaGetSymbolAddress((void**)&tmp, g_tmp);
        cudaGetSymbolAddress((void**)&ff, g_ff);
        cudaGetSymbolAddress((void**)&t, g_t);
        cudaGetSymbolAddress((void**)&part, g_part);
        cudaGetSymbolAddress((void**)&logits, g_logits);
        cudaGetSymbolAddress((void**)&ic2p, g_ic2p);
        cudaGetSymbolAddress((void**)&ip2c, g_ip2c);
        init = true;
    }

    // dynamic smem opt-in (attribute set; not an allocation)
    const int SM_NN  = 2 * (int)sizeof(SmemNN);    // 75776
    const int SM_NT  = 2 * (int)sizeof(SmemNT);    // 81920
    const int SM_CTX = 2 * (int)sizeof(SmemCtx);   // 61440
    cudaFuncSetAttribute(qkvpos_mma,     cudaFuncAttributeMaxDynamicSharedMemorySize, SM_NN);
    cudaFuncSetAttribute(gemm_mma,       cudaFuncAttributeMaxDynamicSharedMemorySize, SM_NN);
    cudaFuncSetAttribute(gemm_mma_split, cudaFuncAttributeMaxDynamicSharedMemorySize, SM_NN);
    cudaFuncSetAttribute(att_mma_kernel, cudaFuncAttributeMaxDynamicSharedMemorySize, SM_NT);
    cudaFuncSetAttribute(ctx_mma_kernel, cudaFuncAttributeMaxDynamicSharedMemorySize, SM_CTX);

    // precompute
    idx_kernel<<<(Ss * Ss + 255) / 256, 256>>>(ic2p, ip2c);
    ln_kernel<<<Rr, 256>>>(rel_emb, rel, rel_ln_s, rel_ln_b);
    embed_kernel<<<Mm, 256>>>(word_emb, input_ids, amask, emb_ln_s, emb_ln_b, x);

    for (int l = 0; l < Ll; l++) {
        const float* Wq_l = Wq + (long)l * Hh * Hh;  const float* bq_l = bq + l * Hh;
        const float* Wk_l = Wk + (long)l * Hh * Hh;  const float* bk_l = bk + l * Hh;
        const float* Wv_l = Wv + (long)l * Hh * Hh;  const float* bv_l = bv + l * Hh;
        const float* Wo_l = Wo + (long)l * Hh * Hh;  const float* bo_l = bo + l * Hh;
        const float* W1_l = W1 + (long)l * Hh * FFf; const float* b1_l = b1 + l * FFf;
        const float* W2_l = W2 + (long)l * FFf * Hh; const float* b2_l = b2 + l * Hh;

        qkvpos_mma<<<dim3(8, 8, 5), 256, SM_NN>>>(
            x, rel, Wq_l, Wk_l, Wv_l, bq_l, bk_l, bv_l, q, k, v, posk, posq);

        att_mma_kernel<<<dim3(4, 4, 96), 256, SM_NT>>>(q, k, posk, posq, sc, c2p, p2c);

        softmax_kernel<<<dim3(Ss, Bb * NHh), 256>>>(sc, c2p, p2c, ic2p, ip2c, amask);

        ctx_mma_kernel<<<dim3(1, 4, Bb * NHh), 256, SM_CTX>>>(sc, v, ctx);

        gemm_mma_split<<<dim3(8, 8, 4), 256, SM_NN>>>(ctx, Wo_l, part, Hh, Hh, 4);
        reduce_bias_kernel<<<(Mm * Hh + 255) / 256, 256>>>(part, bo_l, tmp, Mm, Hh, 4, 0);
        add_ln_kernel<<<Mm, 256>>>(x, tmp, ln1_s + l * Hh, ln1_b + l * Hh);

        gemm_mma<<<dim3(32, 8), 256, SM_NN>>>(x, W1_l, b1_l, ff, FFf, Hh, 1);
        gemm_mma_split<<<dim3(8, 8, 4), 256, SM_NN>>>(ff, W2_l, part, Hh, FFf, 4);
        reduce_bias_kernel<<<(Mm * Hh + 255) / 256, 256>>>(part, b2_l, tmp, Mm, Hh, 4, 0);
        add_ln_kernel<<<Mm, 256>>>(x, tmp, ln2_s + l * Hh, ln2_b + l * Hh);
    }

    // head: transform (GELU) split-K, LN, decoder
    gemm_mma_split<<<dim3(8, 8, 4), 256, SM_NN>>>(x, Wt, part, Hh, Hh, 4);
    reduce_bias_kernel<<<(Mm * Hh + 255) / 256, 256>>>(part, bt, t, Mm, Hh, 4, 1);
    ln_kernel<<<Mm, 256>>>(t, t, tln_s, tln_b);
    gemm_bias_kernel<<<dim3((NCc + BN - 1) / BN, Mm / BM), 256>>>(t, Wd, bd, logits, Mm, NCc, Hh, 0);

    finalize_kernel<<<1, 256>>>(logits, labels, amask, (float*)d_out, out_size);
}